// round 11
// baseline (speedup 1.0000x reference)
#include <cuda_runtime.h>
#include <cuda_bf16.h>
#include <cstdint>

#define N_MAX 100000
#define E_MAX 1600000

// ---------------- static device scratch (no allocations allowed) -------------
__device__ unsigned g_hb[(size_t)N_MAX * 32]; // h in bf16x2 (64 bf16 per node)
__device__ float g_as[N_MAX];                 // a_src per node
__device__ float g_ad[N_MAX];                 // a_dst per node
__device__ int   g_count[N_MAX];              // in-degree histogram
__device__ int   g_off[N_MAX];                // exclusive offsets
__device__ int   g_cur[N_MAX];                // scatter cursors
__device__ int   g_part[256];                 // scan block partials
__device__ int   g_srt[E_MAX];                // edge sources binned by dst
__device__ float g_rsum[64];                  // sum over nodes of relu(agg)
__device__ int   g_is64;                      // 1 if edge buffer is int64 words
__device__ unsigned g_done;                   // agg completion ticket

// ---------------- kernel 1: zero scratch + detect edge width -----------------
__global__ void k_init(const int* __restrict__ ei32, int E, int n) {
    int i = blockIdx.x * blockDim.x + threadIdx.x;
    if (i < n) g_count[i] = 0;
    if (i < 64) g_rsum[i] = 0.f;
    if (i == 0) g_done = 0u;
    if (blockIdx.x == 0 && threadIdx.x < 32) {
        // int64 values < 2^31 have all-zero odd words (LE); int32 ids don't.
        int nz = 0;
        int samples = 2048 < E ? 2048 : E;
        for (int e = (int)threadIdx.x; e < samples; e += 32)
            nz |= ei32[2 * e + 1];
#pragma unroll
        for (int o = 16; o > 0; o >>= 1)
            nz |= __shfl_xor_sync(0xffffffffu, nz, o);
        if (threadIdx.x == 0) g_is64 = (nz == 0) ? 1 : 0;
    }
}

// ---------------- kernel 2: dst histogram (dst row only, 2 edges/thread) -----
__global__ void k_hist(const int* __restrict__ ei, int E, int n) {
    int t2 = blockIdx.x * blockDim.x + threadIdx.x;
    int e = t2 * 2;
    if (e >= E) return;
    bool two = (e + 1 < E);
    int d0, d1 = -1;
    if (g_is64) {
        if (two && (E & 1) == 0) {
            int4 v = ((const int4*)(ei + 2 * (size_t)E))[t2];
            d0 = v.x; d1 = v.z;
        } else {
            d0 = ei[2 * ((size_t)E + e)];
            if (two) d1 = ei[2 * ((size_t)E + e + 1)];
        }
    } else {
        if (two && (E & 1) == 0) {
            int2 v = ((const int2*)(ei + (size_t)E))[t2];
            d0 = v.x; d1 = v.y;
        } else {
            d0 = ei[(size_t)E + e];
            if (two) d1 = ei[(size_t)E + e + 1];
        }
    }
    if ((unsigned)d0 < (unsigned)n) atomicAdd(&g_count[d0], 1);
    if (two && (unsigned)d1 < (unsigned)n) atomicAdd(&g_count[d1], 1);
}

// ---------------- kernels 3,5,6: two-level exclusive scan (proven) -----------
__global__ void __launch_bounds__(1024) k_scan1(int n) {
    __shared__ int wsum[32];
    int tid = threadIdx.x, lane = tid & 31, wid = tid >> 5;
    int gid = blockIdx.x * 1024 + tid;
    int v = (gid < n) ? g_count[gid] : 0;
    int incl = v;
#pragma unroll
    for (int o = 1; o < 32; o <<= 1) {
        int t = __shfl_up_sync(0xffffffffu, incl, o);
        if (lane >= o) incl += t;
    }
    if (lane == 31) wsum[wid] = incl;
    __syncthreads();
    if (wid == 0) {
        int w = wsum[lane];
#pragma unroll
        for (int o = 1; o < 32; o <<= 1) {
            int t = __shfl_up_sync(0xffffffffu, w, o);
            if (lane >= o) w += t;
        }
        wsum[lane] = w;
    }
    __syncthreads();
    int blk_incl = incl + (wid > 0 ? wsum[wid - 1] : 0);
    if (gid < n) g_off[gid] = blk_incl - v;
    if (tid == 1023) g_part[blockIdx.x] = blk_incl;
}

__global__ void k_scan2(int nb) {
    __shared__ int sm[256];
    int tid = threadIdx.x;
    int v = (tid < nb) ? g_part[tid] : 0;
    sm[tid] = v;
    __syncthreads();
    for (int off = 1; off < 256; off <<= 1) {
        int add = 0;
        if (tid >= off) add = sm[tid - off];
        __syncthreads();
        sm[tid] += add;
        __syncthreads();
    }
    if (tid < nb) g_part[tid] = sm[tid] - v;
}

__global__ void k_scan3(int n) {
    int i = blockIdx.x * blockDim.x + threadIdx.x;
    if (i < n) {
        int off = g_off[i] + g_part[i >> 10];
        g_off[i] = off;
        g_cur[i] = off;
    }
}

// ---------------- kernel 4 (PROFILED SLOT): tiled GEMM, double-buffered ------
// Block: 256 threads, tile 128 nodes x 64 cols; thread: 4 nodes x 8 cols,
// 16 f32x2 accumulators. x staged transposed in PING-PONG 8-k chunks: LDG for
// chunk c+1 issued BEFORE computing chunk c, so DRAM latency overlaps compute.
// One __syncthreads per chunk. W in smem; reads = 2 LDS.128, 8 distinct
// addrs/warp. Math core identical to the R10-verified version.
__global__ void __launch_bounds__(256) k_gemm(
    const float* __restrict__ x, const float* __restrict__ W,
    const float* __restrict__ att_s, const float* __restrict__ att_d, int n)
{
    __shared__ unsigned long long Wp[128 * 32];  // 4096 u64 = 32KB (FULL W)
    __shared__ float xs[2][8][128];              // 2 x 4KB ping-pong chunks
    __shared__ float atts[64], attd[64];

    int t = threadIdx.x;
    {   // stage W: 2048 ulonglong2 = 32KB (raw copy; pairs are contiguous)
        ulonglong2* wd = (ulonglong2*)Wp;
        const ulonglong2* wsrc = (const ulonglong2*)W;
        for (int i = t; i < 2048; i += 256) wd[i] = wsrc[i];
        if (t < 64) { atts[t] = att_s[t]; attd[t] = att_d[t]; }
    }

    int tx = t & 7;          // col group: cols 8*tx .. 8*tx+7
    int ty = t >> 3;         // node group: 4 nodes each (32 groups)
    int nodeBase = blockIdx.x * 128 + ty * 4;

    // staging roles: thread loads ONE float4 of x per 8-k chunk
    int sn = t & 127;                       // node slot 0..127
    int kh = t >> 7;                        // which float4 half (k 4*kh..4*kh+3)
    int gnode = blockIdx.x * 128 + sn;
    const float4* xrow = (const float4*)(x + (size_t)(gnode < n ? gnode : (n - 1)) * 128);

    unsigned long long acc2[16];
    {
        float z = 0.f; unsigned long long zp;
        asm("mov.b64 %0, {%1,%1};" : "=l"(zp) : "f"(z));
#pragma unroll
        for (int c = 0; c < 16; c++) acc2[c] = zp;
    }

    const ulonglong2* Wp2 = (const ulonglong2*)Wp;

    // preload + stage chunk 0 (k 0..7)
    float4 r = xrow[kh];
    {
        int kb = kh * 4;
        xs[0][kb + 0][sn] = r.x; xs[0][kb + 1][sn] = r.y;
        xs[0][kb + 2][sn] = r.z; xs[0][kb + 3][sn] = r.w;
    }
    __syncthreads();   // W + chunk0 visible

#pragma unroll 1
    for (int c = 0; c < 16; c++) {
        // issue LDG for chunk c+1 early: overlaps the compute below
        if (c < 15) r = xrow[(c + 1) * 2 + kh];
        int buf = c & 1;

#pragma unroll
        for (int k = 0; k < 8; k++) {
            int kk = c * 8 + k;
            float4 xv = *(const float4*)&xs[buf][k][ty * 4];   // 4 nodes
            ulonglong2 w0 = Wp2[kk * 16 + 2 * tx];             // cols 8tx..8tx+3
            ulonglong2 w1 = Wp2[kk * 16 + 2 * tx + 1];         // cols 8tx+4..+7
            unsigned long long xp0, xp1, xp2, xp3;
            asm("mov.b64 %0, {%1,%1};" : "=l"(xp0) : "f"(xv.x));
            asm("mov.b64 %0, {%1,%1};" : "=l"(xp1) : "f"(xv.y));
            asm("mov.b64 %0, {%1,%1};" : "=l"(xp2) : "f"(xv.z));
            asm("mov.b64 %0, {%1,%1};" : "=l"(xp3) : "f"(xv.w));
            asm("fma.rn.f32x2 %0, %1, %2, %0;" : "+l"(acc2[0])  : "l"(xp0), "l"(w0.x));
            asm("fma.rn.f32x2 %0, %1, %2, %0;" : "+l"(acc2[1])  : "l"(xp0), "l"(w0.y));
            asm("fma.rn.f32x2 %0, %1, %2, %0;" : "+l"(acc2[2])  : "l"(xp0), "l"(w1.x));
            asm("fma.rn.f32x2 %0, %1, %2, %0;" : "+l"(acc2[3])  : "l"(xp0), "l"(w1.y));
            asm("fma.rn.f32x2 %0, %1, %2, %0;" : "+l"(acc2[4])  : "l"(xp1), "l"(w0.x));
            asm("fma.rn.f32x2 %0, %1, %2, %0;" : "+l"(acc2[5])  : "l"(xp1), "l"(w0.y));
            asm("fma.rn.f32x2 %0, %1, %2, %0;" : "+l"(acc2[6])  : "l"(xp1), "l"(w1.x));
            asm("fma.rn.f32x2 %0, %1, %2, %0;" : "+l"(acc2[7])  : "l"(xp1), "l"(w1.y));
            asm("fma.rn.f32x2 %0, %1, %2, %0;" : "+l"(acc2[8])  : "l"(xp2), "l"(w0.x));
            asm("fma.rn.f32x2 %0, %1, %2, %0;" : "+l"(acc2[9])  : "l"(xp2), "l"(w0.y));
            asm("fma.rn.f32x2 %0, %1, %2, %0;" : "+l"(acc2[10]) : "l"(xp2), "l"(w1.x));
            asm("fma.rn.f32x2 %0, %1, %2, %0;" : "+l"(acc2[11]) : "l"(xp2), "l"(w1.y));
            asm("fma.rn.f32x2 %0, %1, %2, %0;" : "+l"(acc2[12]) : "l"(xp3), "l"(w0.x));
            asm("fma.rn.f32x2 %0, %1, %2, %0;" : "+l"(acc2[13]) : "l"(xp3), "l"(w0.y));
            asm("fma.rn.f32x2 %0, %1, %2, %0;" : "+l"(acc2[14]) : "l"(xp3), "l"(w1.x));
            asm("fma.rn.f32x2 %0, %1, %2, %0;" : "+l"(acc2[15]) : "l"(xp3), "l"(w1.y));
        }

        if (c < 15) {   // stage chunk c+1 into the other buffer
            int nb = (c + 1) & 1;
            int kb = kh * 4;
            xs[nb][kb + 0][sn] = r.x; xs[nb][kb + 1][sn] = r.y;
            xs[nb][kb + 2][sn] = r.z; xs[nb][kb + 3][sn] = r.w;
        }
        __syncthreads();
    }

    // epilogue: per node -> bf16 store + partial att dots, reduce over 8 tx lanes
#pragma unroll
    for (int nn = 0; nn < 4; nn++) {
        int node = nodeBase + nn;
        float s = 0.f, d = 0.f;
        unsigned hb[4];
#pragma unroll
        for (int cp = 0; cp < 4; cp++) {
            float lo, hi;
            asm("mov.b64 {%0,%1}, %2;" : "=f"(lo), "=f"(hi) : "l"(acc2[nn * 4 + cp]));
            int c = 8 * tx + 2 * cp;
            s += lo * atts[c] + hi * atts[c + 1];
            d += lo * attd[c] + hi * attd[c + 1];
            __nv_bfloat162 b = __floats2bfloat162_rn(lo, hi);
            hb[cp] = *reinterpret_cast<unsigned*>(&b);
        }
#pragma unroll
        for (int o = 1; o < 8; o <<= 1) {
            s += __shfl_xor_sync(0xffffffffu, s, o);
            d += __shfl_xor_sync(0xffffffffu, d, o);
        }
        if (node < n) {
            *(uint4*)(g_hb + (size_t)node * 32 + 4 * tx) =
                make_uint4(hb[0], hb[1], hb[2], hb[3]);
            if (tx == 0) { g_as[node] = s; g_ad[node] = d; }
        }
    }
}

// ---------------- kernel 7: scatter edges binned by dst (re-decode) ----------
__global__ void k_scatter(const int* __restrict__ ei, int E, int n) {
    int t2 = blockIdx.x * blockDim.x + threadIdx.x;
    int e = t2 * 2;
    if (e >= E) return;
    bool two = (e + 1 < E);
    int s0, d0, s1 = -1, d1 = -1;
    if (g_is64) {
        if (two && (E & 1) == 0) {
            int4 sv = ((const int4*)ei)[t2];
            int4 dv = ((const int4*)(ei + 2 * (size_t)E))[t2];
            s0 = sv.x; s1 = sv.z; d0 = dv.x; d1 = dv.z;
        } else {
            s0 = ei[2 * (size_t)e];
            d0 = ei[2 * ((size_t)E + e)];
            if (two) { s1 = ei[2 * (size_t)(e+1)]; d1 = ei[2 * ((size_t)E + e + 1)]; }
        }
    } else {
        if (two && (E & 1) == 0) {
            int2 sv = ((const int2*)ei)[t2];
            int2 dv = ((const int2*)(ei + (size_t)E))[t2];
            s0 = sv.x; s1 = sv.y; d0 = dv.x; d1 = dv.y;
        } else {
            s0 = ei[e];
            d0 = ei[(size_t)E + e];
            if (two) { s1 = ei[e+1]; d1 = ei[(size_t)E + e + 1]; }
        }
    }
    if ((unsigned)d0 < (unsigned)n) {
        int j = ((unsigned)s0 < (unsigned)n) ? s0 : 0;
        g_srt[atomicAdd(&g_cur[d0], 1)] = j;
    }
    if (two && (unsigned)d1 < (unsigned)n) {
        int j = ((unsigned)s1 < (unsigned)n) ? s1 : 0;
        g_srt[atomicAdd(&g_cur[d1], 1)] = j;
    }
}

// ---------------- kernel 8: warp-per-node aggregation + fused final ----------
// Chunk 32 edges: lane k loads (j, w) coalesced, shfl-broadcast for the bf16 h
// gather (128B/edge). Self loop = virtual edge. No max-shift (logits ~|8|,
// exp safe in fp32, softmax shift-invariant). Last block computes the output.
__global__ void __launch_bounds__(256) k_agg(
    const float* __restrict__ bias, int n,
    const float* __restrict__ Wl, const float* __restrict__ bl,
    float* __restrict__ out, float invn)
{
    __shared__ float rs[64];
    __shared__ int slast;
    int t = threadIdx.x;
    if (t < 64) rs[t] = 0.f;
    __syncthreads();

    int warp = (blockIdx.x * 256 + t) >> 5;
    int l = t & 31;
    if (warp < n) {
        int i = warp;
        int start = g_off[i];
        int len = g_count[i];
        float adi = g_ad[i];
        float accx = 0.f, accy = 0.f, den = 0.f;
        int total = len + 1;                       // + self loop
        for (int base = 0; base < total; base += 32) {
            int k = base + l;
            int j = i; float wv = 0.f;
            if (k < total) {
                if (k < len) j = g_srt[start + k];  // coalesced
                float v = g_as[j] + adi;
                v = v > 0.f ? v : 0.2f * v;
                wv = __expf(v);
            }
            den += wv;
            int m = total - base; if (m > 32) m = 32;
            if (m == 32) {
#pragma unroll
                for (int kk = 0; kk < 32; kk++) {
                    int jj  = __shfl_sync(0xffffffffu, j,  kk);
                    float w = __shfl_sync(0xffffffffu, wv, kk);
                    unsigned p = g_hb[(size_t)jj * 32 + l];
                    float2 hv = __bfloat1622float2(*reinterpret_cast<__nv_bfloat162*>(&p));
                    accx += w * hv.x;
                    accy += w * hv.y;
                }
            } else {
                for (int kk = 0; kk < m; kk++) {
                    int jj  = __shfl_sync(0xffffffffu, j,  kk);
                    float w = __shfl_sync(0xffffffffu, wv, kk);
                    unsigned p = g_hb[(size_t)jj * 32 + l];
                    float2 hv = __bfloat1622float2(*reinterpret_cast<__nv_bfloat162*>(&p));
                    accx += w * hv.x;
                    accy += w * hv.y;
                }
            }
        }
#pragma unroll
        for (int o = 16; o > 0; o >>= 1)
            den += __shfl_xor_sync(0xffffffffu, den, o);
        float inv = 1.f / den;
        float r0 = accx * inv + bias[2*l];     r0 = r0 > 0.f ? r0 : 0.f;
        float r1 = accy * inv + bias[2*l+1];   r1 = r1 > 0.f ? r1 : 0.f;
        atomicAdd(&rs[2*l],     r0);
        atomicAdd(&rs[2*l + 1], r1);
    }
    __syncthreads();
    if (t < 64) atomicAdd(&g_rsum[t], rs[t]);

    // last-block-done: fused final GEMV out = (rsum/N) @ W_lin + b_lin
    __threadfence();
    if (t == 0) {
        unsigned d = atomicAdd(&g_done, 1u);
        slast = (d == gridDim.x - 1) ? 1 : 0;
    }
    __syncthreads();
    if (slast && t < 64) {
        __threadfence();
        float s = 0.f;
#pragma unroll 4
        for (int c = 0; c < 64; c++) s += g_rsum[c] * Wl[c * 64 + t];
        out[t] = s * invn + bl[t];
    }
}

// ---------------- launcher ---------------------------------------------------
extern "C" void kernel_launch(void* const* d_in, const int* in_sizes, int n_in,
                              void* d_out, int out_size) {
    const float* x    = (const float*)d_in[0];
    const int*   ei   = (const int*)d_in[1];     // int32 OR int64 words (probed)
    const float* W    = (const float*)d_in[2];
    const float* atts = (const float*)d_in[3];
    const float* attd = (const float*)d_in[4];
    const float* bc   = (const float*)d_in[5];
    const float* Wl   = (const float*)d_in[6];
    const float* bl   = (const float*)d_in[7];
    float*       out  = (float*)d_out;

    int n = in_sizes[0] / 128;   // nodes
    int E = in_sizes[1] / 2;     // edges ([2, E] layout)
    if (n > N_MAX) n = N_MAX;
    if (E > E_MAX) E = E_MAX;

    int nb1 = (n + 1023) / 1024;
    int Epairs = (E + 1) / 2;

    k_init   <<<(n + 255) / 256, 256>>>(ei, E, n);
    k_hist   <<<(Epairs + 255) / 256, 256>>>(ei, E, n);
    k_scan1  <<<nb1, 1024>>>(n);
    k_gemm   <<<(n + 127) / 128, 256>>>(x, W, atts, attd, n);   // launch #4 -> profiled
    k_scan2  <<<1, 256>>>(nb1);
    k_scan3  <<<(n + 255) / 256, 256>>>(n);
    k_scatter<<<(Epairs + 255) / 256, 256>>>(ei, E, n);
    k_agg    <<<(n + 7) / 8, 256>>>(bc, n, Wl, bl, out, 1.f / (float)n);
}

// round 12
// speedup vs baseline: 1.2900x; 1.2900x over previous
#include <cuda_runtime.h>
#include <cuda_bf16.h>
#include <cstdint>

#define N_MAX 100000
#define E_MAX 1600000

// ---------------- static device scratch (no allocations allowed) -------------
__device__ unsigned g_hb[(size_t)N_MAX * 32]; // h in bf16x2 (64 bf16 per node)
__device__ float g_as[N_MAX];                 // a_src per node
__device__ float g_ad[N_MAX];                 // a_dst per node
__device__ int   g_count[N_MAX];              // in-degree histogram
__device__ int   g_off[N_MAX];                // exclusive offsets
__device__ int   g_cur[N_MAX];                // scatter cursors
__device__ int   g_part[256];                 // scan block partials
__device__ int   g_srt[E_MAX];                // edge sources binned by dst
__device__ float g_rsum[64];                  // sum over nodes of relu(agg)
__device__ int   g_is64;                      // 1 if edge buffer is int64 words
__device__ unsigned g_done;                   // agg completion ticket

// ---------------- kernel 1: zero scratch + detect edge width -----------------
__global__ void k_init(const int* __restrict__ ei32, int E, int n) {
    int i = blockIdx.x * blockDim.x + threadIdx.x;
    if (i < n) g_count[i] = 0;
    if (i < 64) g_rsum[i] = 0.f;
    if (i == 0) g_done = 0u;
    if (blockIdx.x == 0 && threadIdx.x < 32) {
        // int64 values < 2^31 have all-zero odd words (LE); int32 ids don't.
        int nz = 0;
        int samples = 2048 < E ? 2048 : E;
        for (int e = (int)threadIdx.x; e < samples; e += 32)
            nz |= ei32[2 * e + 1];
#pragma unroll
        for (int o = 16; o > 0; o >>= 1)
            nz |= __shfl_xor_sync(0xffffffffu, nz, o);
        if (threadIdx.x == 0) g_is64 = (nz == 0) ? 1 : 0;
    }
}

// ---------------- kernel 2: dst histogram (dst row only, 2 edges/thread) -----
__global__ void k_hist(const int* __restrict__ ei, int E, int n) {
    int t2 = blockIdx.x * blockDim.x + threadIdx.x;
    int e = t2 * 2;
    if (e >= E) return;
    bool two = (e + 1 < E);
    int d0, d1 = -1;
    if (g_is64) {
        if (two && (E & 1) == 0) {
            int4 v = ((const int4*)(ei + 2 * (size_t)E))[t2];
            d0 = v.x; d1 = v.z;
        } else {
            d0 = ei[2 * ((size_t)E + e)];
            if (two) d1 = ei[2 * ((size_t)E + e + 1)];
        }
    } else {
        if (two && (E & 1) == 0) {
            int2 v = ((const int2*)(ei + (size_t)E))[t2];
            d0 = v.x; d1 = v.y;
        } else {
            d0 = ei[(size_t)E + e];
            if (two) d1 = ei[(size_t)E + e + 1];
        }
    }
    if ((unsigned)d0 < (unsigned)n) atomicAdd(&g_count[d0], 1);
    if (two && (unsigned)d1 < (unsigned)n) atomicAdd(&g_count[d1], 1);
}

// ---------------- kernels 3,5,6: two-level exclusive scan (proven) -----------
__global__ void __launch_bounds__(1024) k_scan1(int n) {
    __shared__ int wsum[32];
    int tid = threadIdx.x, lane = tid & 31, wid = tid >> 5;
    int gid = blockIdx.x * 1024 + tid;
    int v = (gid < n) ? g_count[gid] : 0;
    int incl = v;
#pragma unroll
    for (int o = 1; o < 32; o <<= 1) {
        int t = __shfl_up_sync(0xffffffffu, incl, o);
        if (lane >= o) incl += t;
    }
    if (lane == 31) wsum[wid] = incl;
    __syncthreads();
    if (wid == 0) {
        int w = wsum[lane];
#pragma unroll
        for (int o = 1; o < 32; o <<= 1) {
            int t = __shfl_up_sync(0xffffffffu, w, o);
            if (lane >= o) w += t;
        }
        wsum[lane] = w;
    }
    __syncthreads();
    int blk_incl = incl + (wid > 0 ? wsum[wid - 1] : 0);
    if (gid < n) g_off[gid] = blk_incl - v;
    if (tid == 1023) g_part[blockIdx.x] = blk_incl;
}

__global__ void k_scan2(int nb) {
    __shared__ int sm[256];
    int tid = threadIdx.x;
    int v = (tid < nb) ? g_part[tid] : 0;
    sm[tid] = v;
    __syncthreads();
    for (int off = 1; off < 256; off <<= 1) {
        int add = 0;
        if (tid >= off) add = sm[tid - off];
        __syncthreads();
        sm[tid] += add;
        __syncthreads();
    }
    if (tid < nb) g_part[tid] = sm[tid] - v;
}

__global__ void k_scan3(int n) {
    int i = blockIdx.x * blockDim.x + threadIdx.x;
    if (i < n) {
        int off = g_off[i] + g_part[i >> 10];
        g_off[i] = off;
        g_cur[i] = off;
    }
}

// ---------------- kernel 4 (PROFILED SLOT): tf32 tensor-core GEMM ------------
// h = x@W via mma.sync.m16n8k8.tf32. Block: 256 thr = 8 warps, tile 128 nodes
// x 64 cols; warp: 16 nodes x 64 cols (8 n-tiles), 32 fp32 accs.
// W staged tf32-rounded in smem with 72-float row pad (B reads conflict-free:
// bank = 8*tig + gid, all 32 distinct). x staged transposed-free as
// xs[node][k8] (A reads 2-way conflict, 4 LDS/chunk -> negligible), ping-pong
// double buffered. Fragments (PTX m16n8k8.tf32, gid=lane/4, tig=lane%4):
//   A: a0(r=gid,c=tig) a1(r=gid+8,c=tig) a2(r=gid,c=tig+4) a3(r=gid+8,c=tig+4)
//   B: b0(k=tig,n=gid) b1(k=tig+4,n=gid)
//   C: c0(r=gid,c=2tig) c1(+1) c2(r=gid+8,c=2tig) c3(+1)
__global__ void __launch_bounds__(256) k_gemm(
    const float* __restrict__ x, const float* __restrict__ W,
    const float* __restrict__ att_s, const float* __restrict__ att_d, int n)
{
    __shared__ float Wt[128 * 72];     // 36 KB, tf32-rounded
    __shared__ float xs[2][128][8];    // 8 KB ping-pong
    __shared__ float atts[64], attd[64];

    int t = threadIdx.x;
    int warp = t >> 5, lane = t & 31;
    int gid = lane >> 2, tig = lane & 3;

    // stage W with tf32 rounding
    for (int i = t; i < 8192; i += 256) {
        int k = i >> 6, c = i & 63;
        unsigned tv;
        asm("cvt.rna.tf32.f32 %0, %1;" : "=r"(tv) : "f"(W[i]));
        Wt[k * 72 + c] = __uint_as_float(tv);
    }
    if (t < 64) { atts[t] = att_s[t]; attd[t] = att_d[t]; }

    // x staging roles: thread loads one float4 per chunk
    int snode = t >> 1;                 // node slot 0..127
    int half = t & 1;                   // which float4 of the 8-k chunk
    int gnode = blockIdx.x * 128 + snode;
    const float4* xrow = (const float4*)(x + (size_t)(gnode < n ? gnode : (n - 1)) * 128);

    float acc[32];
#pragma unroll
    for (int i = 0; i < 32; i++) acc[i] = 0.f;

    // preload + stage chunk 0
    float4 r = xrow[half];
    *(float4*)&xs[0][snode][half * 4] = r;
    __syncthreads();   // W + chunk0 visible

    int arow0 = warp * 16 + gid;        // A rows within block tile
#pragma unroll 1
    for (int c = 0; c < 16; c++) {
        if (c < 15) r = xrow[(c + 1) * 2 + half];
        int buf = c & 1;

        unsigned a0, a1, a2, a3;
        asm("cvt.rna.tf32.f32 %0, %1;" : "=r"(a0) : "f"(xs[buf][arow0][tig]));
        asm("cvt.rna.tf32.f32 %0, %1;" : "=r"(a1) : "f"(xs[buf][arow0 + 8][tig]));
        asm("cvt.rna.tf32.f32 %0, %1;" : "=r"(a2) : "f"(xs[buf][arow0][tig + 4]));
        asm("cvt.rna.tf32.f32 %0, %1;" : "=r"(a3) : "f"(xs[buf][arow0 + 8][tig + 4]));

#pragma unroll
        for (int nt = 0; nt < 8; nt++) {
            unsigned b0 = __float_as_uint(Wt[(c * 8 + tig) * 72 + nt * 8 + gid]);
            unsigned b1 = __float_as_uint(Wt[(c * 8 + tig + 4) * 72 + nt * 8 + gid]);
            asm("mma.sync.aligned.m16n8k8.row.col.f32.tf32.tf32.f32 "
                "{%0,%1,%2,%3}, {%4,%5,%6,%7}, {%8,%9}, {%0,%1,%2,%3};"
                : "+f"(acc[nt*4+0]), "+f"(acc[nt*4+1]),
                  "+f"(acc[nt*4+2]), "+f"(acc[nt*4+3])
                : "r"(a0), "r"(a1), "r"(a2), "r"(a3), "r"(b0), "r"(b1));
        }

        if (c < 15)
            *(float4*)&xs[(c + 1) & 1][snode][half * 4] = r;
        __syncthreads();
    }

    // epilogue: 2 rows per thread; cols 2tig,2tig+1 per n-tile (bf16x2 pair)
    int row0 = blockIdx.x * 128 + arow0;
    int row1 = row0 + 8;
    float s0 = 0.f, d0 = 0.f, s1 = 0.f, d1 = 0.f;
#pragma unroll
    for (int nt = 0; nt < 8; nt++) {
        int col = nt * 8 + 2 * tig;
        float c0 = acc[nt*4+0], c1 = acc[nt*4+1];
        float c2 = acc[nt*4+2], c3 = acc[nt*4+3];
        s0 += c0 * atts[col] + c1 * atts[col + 1];
        d0 += c0 * attd[col] + c1 * attd[col + 1];
        s1 += c2 * atts[col] + c3 * atts[col + 1];
        d1 += c2 * attd[col] + c3 * attd[col + 1];
        if (row0 < n) {
            __nv_bfloat162 b = __floats2bfloat162_rn(c0, c1);
            g_hb[(size_t)row0 * 32 + nt * 4 + tig] = *reinterpret_cast<unsigned*>(&b);
        }
        if (row1 < n) {
            __nv_bfloat162 b = __floats2bfloat162_rn(c2, c3);
            g_hb[(size_t)row1 * 32 + nt * 4 + tig] = *reinterpret_cast<unsigned*>(&b);
        }
    }
    // reduce over the 4 lanes (tig) sharing each row
#pragma unroll
    for (int o = 1; o < 4; o <<= 1) {
        s0 += __shfl_xor_sync(0xffffffffu, s0, o);
        d0 += __shfl_xor_sync(0xffffffffu, d0, o);
        s1 += __shfl_xor_sync(0xffffffffu, s1, o);
        d1 += __shfl_xor_sync(0xffffffffu, d1, o);
    }
    if (tig == 0) {
        if (row0 < n) { g_as[row0] = s0; g_ad[row0] = d0; }
        if (row1 < n) { g_as[row1] = s1; g_ad[row1] = d1; }
    }
}

// ---------------- kernel 7: scatter edges binned by dst (re-decode) ----------
__global__ void k_scatter(const int* __restrict__ ei, int E, int n) {
    int t2 = blockIdx.x * blockDim.x + threadIdx.x;
    int e = t2 * 2;
    if (e >= E) return;
    bool two = (e + 1 < E);
    int s0, d0, s1 = -1, d1 = -1;
    if (g_is64) {
        if (two && (E & 1) == 0) {
            int4 sv = ((const int4*)ei)[t2];
            int4 dv = ((const int4*)(ei + 2 * (size_t)E))[t2];
            s0 = sv.x; s1 = sv.z; d0 = dv.x; d1 = dv.z;
        } else {
            s0 = ei[2 * (size_t)e];
            d0 = ei[2 * ((size_t)E + e)];
            if (two) { s1 = ei[2 * (size_t)(e+1)]; d1 = ei[2 * ((size_t)E + e + 1)]; }
        }
    } else {
        if (two && (E & 1) == 0) {
            int2 sv = ((const int2*)ei)[t2];
            int2 dv = ((const int2*)(ei + (size_t)E))[t2];
            s0 = sv.x; s1 = sv.y; d0 = dv.x; d1 = dv.y;
        } else {
            s0 = ei[e];
            d0 = ei[(size_t)E + e];
            if (two) { s1 = ei[e+1]; d1 = ei[(size_t)E + e + 1]; }
        }
    }
    if ((unsigned)d0 < (unsigned)n) {
        int j = ((unsigned)s0 < (unsigned)n) ? s0 : 0;
        g_srt[atomicAdd(&g_cur[d0], 1)] = j;
    }
    if (two && (unsigned)d1 < (unsigned)n) {
        int j = ((unsigned)s1 < (unsigned)n) ? s1 : 0;
        g_srt[atomicAdd(&g_cur[d1], 1)] = j;
    }
}

// ---------------- kernel 8: warp-per-node aggregation + fused final ----------
// Chunk 32 edges: lane k loads (j, w) coalesced, shfl-broadcast for the bf16 h
// gather (128B/edge). Self loop = virtual edge. No max-shift (logits ~|8|,
// exp safe in fp32, softmax shift-invariant). Last block computes the output.
__global__ void __launch_bounds__(256) k_agg(
    const float* __restrict__ bias, int n,
    const float* __restrict__ Wl, const float* __restrict__ bl,
    float* __restrict__ out, float invn)
{
    __shared__ float rs[64];
    __shared__ int slast;
    int t = threadIdx.x;
    if (t < 64) rs[t] = 0.f;
    __syncthreads();

    int warp = (blockIdx.x * 256 + t) >> 5;
    int l = t & 31;
    if (warp < n) {
        int i = warp;
        int start = g_off[i];
        int len = g_count[i];
        float adi = g_ad[i];
        float accx = 0.f, accy = 0.f, den = 0.f;
        int total = len + 1;                       // + self loop
        for (int base = 0; base < total; base += 32) {
            int k = base + l;
            int j = i; float wv = 0.f;
            if (k < total) {
                if (k < len) j = g_srt[start + k];  // coalesced
                float v = g_as[j] + adi;
                v = v > 0.f ? v : 0.2f * v;
                wv = __expf(v);
            }
            den += wv;
            int m = total - base; if (m > 32) m = 32;
            if (m == 32) {
#pragma unroll
                for (int kk = 0; kk < 32; kk++) {
                    int jj  = __shfl_sync(0xffffffffu, j,  kk);
                    float w = __shfl_sync(0xffffffffu, wv, kk);
                    unsigned p = g_hb[(size_t)jj * 32 + l];
                    float2 hv = __bfloat1622float2(*reinterpret_cast<__nv_bfloat162*>(&p));
                    accx += w * hv.x;
                    accy += w * hv.y;
                }
            } else {
                for (int kk = 0; kk < m; kk++) {
                    int jj  = __shfl_sync(0xffffffffu, j,  kk);
                    float w = __shfl_sync(0xffffffffu, wv, kk);
                    unsigned p = g_hb[(size_t)jj * 32 + l];
                    float2 hv = __bfloat1622float2(*reinterpret_cast<__nv_bfloat162*>(&p));
                    accx += w * hv.x;
                    accy += w * hv.y;
                }
            }
        }
#pragma unroll
        for (int o = 16; o > 0; o >>= 1)
            den += __shfl_xor_sync(0xffffffffu, den, o);
        float inv = 1.f / den;
        float r0 = accx * inv + bias[2*l];     r0 = r0 > 0.f ? r0 : 0.f;
        float r1 = accy * inv + bias[2*l+1];   r1 = r1 > 0.f ? r1 : 0.f;
        atomicAdd(&rs[2*l],     r0);
        atomicAdd(&rs[2*l + 1], r1);
    }
    __syncthreads();
    if (t < 64) atomicAdd(&g_rsum[t], rs[t]);

    // last-block-done: fused final GEMV out = (rsum/N) @ W_lin + b_lin
    __threadfence();
    if (t == 0) {
        unsigned d = atomicAdd(&g_done, 1u);
        slast = (d == gridDim.x - 1) ? 1 : 0;
    }
    __syncthreads();
    if (slast && t < 64) {
        __threadfence();
        float s = 0.f;
#pragma unroll 4
        for (int c = 0; c < 64; c++) s += g_rsum[c] * Wl[c * 64 + t];
        out[t] = s * invn + bl[t];
    }
}

// ---------------- launcher ---------------------------------------------------
extern "C" void kernel_launch(void* const* d_in, const int* in_sizes, int n_in,
                              void* d_out, int out_size) {
    const float* x    = (const float*)d_in[0];
    const int*   ei   = (const int*)d_in[1];     // int32 OR int64 words (probed)
    const float* W    = (const float*)d_in[2];
    const float* atts = (const float*)d_in[3];
    const float* attd = (const float*)d_in[4];
    const float* bc   = (const float*)d_in[5];
    const float* Wl   = (const float*)d_in[6];
    const float* bl   = (const float*)d_in[7];
    float*       out  = (float*)d_out;

    int n = in_sizes[0] / 128;   // nodes
    int E = in_sizes[1] / 2;     // edges ([2, E] layout)
    if (n > N_MAX) n = N_MAX;
    if (E > E_MAX) E = E_MAX;

    int nb1 = (n + 1023) / 1024;
    int Epairs = (E + 1) / 2;

    k_init   <<<(n + 255) / 256, 256>>>(ei, E, n);
    k_hist   <<<(Epairs + 255) / 256, 256>>>(ei, E, n);
    k_scan1  <<<nb1, 1024>>>(n);
    k_gemm   <<<(n + 127) / 128, 256>>>(x, W, atts, attd, n);   // launch #4 -> profiled
    k_scan2  <<<1, 256>>>(nb1);
    k_scan3  <<<(n + 255) / 256, 256>>>(n);
    k_scatter<<<(Epairs + 255) / 256, 256>>>(ei, E, n);
    k_agg    <<<(n + 7) / 8, 256>>>(bc, n, Wl, bl, out, 1.f / (float)n);
}